// round 12
// baseline (speedup 1.0000x reference)
#include <cuda_runtime.h>
#include <cstdint>

#define BATCH 8
#define CH    256
#define HH    96
#define WW    96
#define HW    (HH*WW)
#define DMAX  4
#define DD    9
#define NSH   81
#define TILE_W 32
#define TILE_H 8
#define NTHR  192                       // (8,8,3)
#define CC    4
#define NCHUNK (CH/CC)                  // 64
#define HALO_H 16
#define HALO_W 40                       // pure LDS.128 phases are contiguous 128B rows
#define F1_WORDS (CC*HALO_H*HALO_W)     // 2560
#define F0_WORDS (CC*TILE_H*TILE_W)     // 1024
#define BUF_WORDS (F1_WORDS+F0_WORDS)   // 3584
#define NBUF 4
#define MBAR_BYTE (NBUF*BUF_WORDS*4)    // 57344
#define SMEM_BYTES (MBAR_BYTE + 64)     // + 8 mbarriers
#define NF16_F1 (F1_WORDS/4)            // 640 16B copies -> 3 + 1 predicated per thread
#define NF16_F0 (F0_WORDS/4)            // 256 16B copies

typedef unsigned long long u64;

__device__ __forceinline__ void cp16z(uint32_t dst, const void* src, int sz) {
    asm volatile("cp.async.cg.shared.global [%0], [%1], 16, %2;\n"
                 :: "r"(dst), "l"(src), "r"(sz));
}
__device__ __forceinline__ void cp16(uint32_t dst, const void* src) {
    asm volatile("cp.async.cg.shared.global [%0], [%1], 16;\n"
                 :: "r"(dst), "l"(src));
}
__device__ __forceinline__ void lds128(u64& a, u64& b, uint32_t addr) {
    asm volatile("ld.shared.v2.b64 {%0, %1}, [%2];"
                 : "=l"(a), "=l"(b) : "r"(addr));
}
__device__ __forceinline__ void ffma2(u64& acc, u64 a, u64 b) {
    asm("fma.rn.f32x2 %0, %1, %2, %3;" : "=l"(acc) : "l"(a), "l"(b), "l"(acc));
}
__device__ __forceinline__ u64 pack2(float x, float y) {
    u64 d; asm("mov.b64 %0, {%1, %2};" : "=l"(d) : "f"(x), "f"(y)); return d;
}
__device__ __forceinline__ void unpack2(u64 d, float& x, float& y) {
    asm("mov.b64 {%0, %1}, %2;" : "=f"(x), "=f"(y) : "l"(d));
}
__device__ __forceinline__ float lo32(u64 d) { float x,y; unpack2(d,x,y); return x; }
__device__ __forceinline__ float hi32(u64 d) { float x,y; unpack2(d,x,y); return y; }

__device__ __forceinline__ void mbar_init(uint32_t addr, uint32_t cnt) {
    asm volatile("mbarrier.init.shared.b64 [%0], %1;" :: "r"(addr), "r"(cnt) : "memory");
}
__device__ __forceinline__ void marrive(uint32_t addr) {
    asm volatile("mbarrier.arrive.shared.b64 _, [%0];" :: "r"(addr) : "memory");
}
__device__ __forceinline__ void cparrive(uint32_t addr) {
    asm volatile("cp.async.mbarrier.arrive.noinc.shared.b64 [%0];" :: "r"(addr) : "memory");
}
__device__ __forceinline__ void mwait(uint32_t addr, uint32_t parity) {
    asm volatile(
        "{\n\t.reg .pred P;\n\t"
        "WL_%=:\n\t"
        "mbarrier.try_wait.parity.acquire.cta.shared::cta.b64 P, [%0], %1, 0x989680;\n\t"
        "@!P bra WL_%=;\n\t"
        "}" :: "r"(addr), "r"(parity) : "memory");
}

__global__ __launch_bounds__(NTHR, 2)
void corr_kernel(const float* __restrict__ FM0,
                 const float* __restrict__ FM1,
                 float* __restrict__ out)
{
    extern __shared__ float smem[];     // NBUF bufs + mbarriers

    const int tx  = threadIdx.x;          // 0..7  : 4 pixels each
    const int ty  = threadIdx.y;          // 0..7  : pixel row
    const int tz  = threadIdx.z;          // 0..2  : shift-row group (di = 3tz..3tz+2)
    const int tid = (tz * TILE_H + ty) * 8 + tx;
    const int w0  = blockIdx.x * TILE_W;
    const int h0  = blockIdx.y * TILE_H;
    const int b   = blockIdx.z;

    // ---- FM1 halo gather table: 3 + 1 predicated 16B cp.async per thread ----
    int dstw[4], srcw[4];
#pragma unroll
    for (int j = 0; j < 4; j++) {
        int idx = tid + NTHR * j;             // valid iff < 640
        int cc  = idx / (HALO_H * (HALO_W/4));
        int rem = idx - cc * (HALO_H * (HALO_W/4));
        int r   = rem / (HALO_W/4);
        int c4  = rem - r * (HALO_W/4);
        dstw[j] = (cc * HALO_H + r) * HALO_W + 4 * c4;
        int gh = h0 - DMAX + r;
        int gw = w0 - DMAX + 4 * c4;          // 4-aligned: fully in or out of [0,96)
        srcw[j] = ((unsigned)gh < HH && (unsigned)gw < WW)
                    ? cc * HW + gh * WW + gw : -1;
    }
    const bool f1v3 = (tid < NF16_F1 - 3 * NTHR); // tid < 64

    // ---- FM0 stage mapping: 16B copies (256 total; threads 0..63 do two) ----
    const float* f0base = FM0 + (size_t)b * CH * HW;
    int f0dst[2]; size_t f0off[2];
#pragma unroll
    for (int j = 0; j < 2; j++) {
        int idx = tid + NTHR * j;             // valid iff < 256
        int cc  = idx >> 6;
        int rem = idx & 63;
        int row = rem >> 3;
        int c4  = rem & 7;
        f0dst[j] = F1_WORDS + (cc * TILE_H + row) * TILE_W + 4 * c4;
        f0off[j] = (size_t)cc * HW + (size_t)(h0 + row) * WW + w0 + 4 * c4;
    }
    const bool f0v1 = (tid < NF16_F0 - NTHR); // tid < 64

    const float* f1b = FM1 + (size_t)b * CH * HW;
    const uint32_t sbase = (uint32_t)__cvta_generic_to_shared(smem);
    const uint32_t mfull  = sbase + MBAR_BYTE;        // full[i]  at +i*8
    const uint32_t mempty = sbase + MBAR_BYTE + 32;   // empty[i] at +i*8

    if (tid == 0) {
#pragma unroll
        for (int i = 0; i < NBUF; i++) {
            mbar_init(mfull  + i * 8, NTHR);
            mbar_init(mempty + i * 8, NTHR);
        }
    }
    __syncthreads();

    auto issue = [&](int c0, uint32_t buf) {
        uint32_t base = sbase + buf * (BUF_WORDS * 4u);
#pragma unroll
        for (int j = 0; j < 4; j++) {
            if (j < 3 || f1v3) {
                int sw = srcw[j];
                const float* s = f1b + (size_t)c0 * HW + (sw < 0 ? 0 : sw);
                cp16z(base + (uint32_t)dstw[j] * 4u, s, sw < 0 ? 0 : 16);
            }
        }
        cp16(base + (uint32_t)f0dst[0] * 4u, f0base + f0off[0] + (size_t)c0 * HW);
        if (f0v1)
            cp16(base + (uint32_t)f0dst[1] * 4u, f0base + f0off[1] + (size_t)c0 * HW);
    };

    // Accumulators: P[r][px][pair], S[r][px]  (3 rows x 4 px x (4 f32x2 + 1 scalar))
    u64   P[3][4][4];
    float S[3][4];
#pragma unroll
    for (int r = 0; r < 3; r++) {
#pragma unroll
        for (int i = 0; i < 4; i++) {
            S[r][i] = 0.f;
#pragma unroll
            for (int p = 0; p < 4; p++) P[r][i][p] = 0ull;
        }
    }

    // byte offset of this thread's row base within a buffer
    const uint32_t rowbyte0 = (uint32_t)(((ty + 3 * tz) * HALO_W + 4 * tx) * 4);

    // ---- prologue: stage chunks 0..2 into bufs 0..2 (no empty-wait: fresh) ----
    issue(0 * CC, 0); cparrive(mfull + 0);
    issue(1 * CC, 1); cparrive(mfull + 8);
    issue(2 * CC, 2); cparrive(mfull + 16);

#pragma unroll 1
    for (int ci = 0; ci < NCHUNK; ci++) {
        const uint32_t buf = (uint32_t)(ci & 3);
        // data for chunk ci ready? (192 cp-completion arrivals)
        mwait(mfull + buf * 8, (uint32_t)((ci >> 2) & 1));

        const float* sb = &smem[buf * BUF_WORDS];
        const uint32_t sboff = sbase + buf * (BUF_WORDS * 4u) + rowbyte0;
#pragma unroll
        for (int cc = 0; cc < CC; cc++) {
            float4 f0 = *(const float4*)(sb + F1_WORDS +
                                         (cc * TILE_H + ty) * TILE_W + 4 * tx);
            const u64 fa0 = pack2(f0.x, f0.x);
            const u64 fa1 = pack2(f0.y, f0.y);
            const u64 fa2 = pack2(f0.z, f0.z);
            const u64 fa3 = pack2(f0.w, f0.w);
            const uint32_t rowa = sboff + (uint32_t)(cc * HALO_H * HALO_W) * 4u;
#pragma unroll
            for (int r = 0; r < 3; r++) {
                const uint32_t a = rowa + (uint32_t)(r * HALO_W) * 4u;
                u64 v0, v1, v2, v3, v4, v5;
                lds128(v0, v1, a);
                lds128(v2, v3, a + 16);
                lds128(v4, v5, a + 32);
                // px0 (cols 4tx+0..8): pairs v0..v3, scalar dj8 = v4.lo
                ffma2(P[r][0][0], fa0, v0); ffma2(P[r][0][1], fa0, v1);
                ffma2(P[r][0][2], fa0, v2); ffma2(P[r][0][3], fa0, v3);
                S[r][0] = fmaf(f0.x, lo32(v4), S[r][0]);
                // px1 (cols 4tx+1..9): scalar dj0 = v0.hi, pairs v1..v4
                ffma2(P[r][1][0], fa1, v1); ffma2(P[r][1][1], fa1, v2);
                ffma2(P[r][1][2], fa1, v3); ffma2(P[r][1][3], fa1, v4);
                S[r][1] = fmaf(f0.y, hi32(v0), S[r][1]);
                // px2 (cols 4tx+2..10): pairs v1..v4, scalar dj8 = v5.lo
                ffma2(P[r][2][0], fa2, v1); ffma2(P[r][2][1], fa2, v2);
                ffma2(P[r][2][2], fa2, v3); ffma2(P[r][2][3], fa2, v4);
                S[r][2] = fmaf(f0.z, lo32(v5), S[r][2]);
                // px3 (cols 4tx+3..11): scalar dj0 = v1.hi, pairs v2..v5
                ffma2(P[r][3][0], fa3, v2); ffma2(P[r][3][1], fa3, v3);
                ffma2(P[r][3][2], fa3, v4); ffma2(P[r][3][3], fa3, v5);
                S[r][3] = fmaf(f0.w, hi32(v1), S[r][3]);
            }
        }

        marrive(mempty + buf * 8);      // this thread done reading buf

        const int cn = ci + 3;
        if (cn < NCHUNK) {
            const uint32_t nb = (uint32_t)(cn & 3);
            // all readers of chunk cn-4 (same buf) must be done before overwrite
            if (cn >= 4)
                mwait(mempty + nb * 8, (uint32_t)(((cn >> 2) & 1) ^ 1));
            issue(cn * CC, nb);
            cparrive(mfull + nb * 8);
        }
    }

    // ---- coalesced output: 4 tile-rows per staging pass (2 passes) ----
#pragma unroll 1
    for (int g = 0; g < 2; g++) {
        __syncthreads();   // pass 0: everyone past mainloop; pass 1: copies done
        if ((ty >> 2) == g) {
            float* st = &smem[(size_t)((ty & 3) * TILE_W + 4 * tx) * NSH];
#pragma unroll
            for (int r = 0; r < 3; r++) {
                const int base = (3 * tz + r) * DD;
                float x, y;
#pragma unroll
                for (int p = 0; p < 4; p++) {
                    unpack2(P[r][0][p], x, y);
                    st[0 * NSH + base + 2 * p]     = x;
                    st[0 * NSH + base + 2 * p + 1] = y;
                    unpack2(P[r][1][p], x, y);
                    st[1 * NSH + base + 2 * p + 1] = x;
                    st[1 * NSH + base + 2 * p + 2] = y;
                    unpack2(P[r][2][p], x, y);
                    st[2 * NSH + base + 2 * p]     = x;
                    st[2 * NSH + base + 2 * p + 1] = y;
                    unpack2(P[r][3][p], x, y);
                    st[3 * NSH + base + 2 * p + 1] = x;
                    st[3 * NSH + base + 2 * p + 2] = y;
                }
                st[0 * NSH + base + 8] = S[r][0];
                st[1 * NSH + base + 0] = S[r][1];
                st[2 * NSH + base + 8] = S[r][2];
                st[3 * NSH + base + 0] = S[r][3];
            }
        }
        __syncthreads();
        // copy 4 rows (10368 words) to gmem; out rows stride WW*NSH
        const float4* src = (const float4*)smem;
        for (int i = tid; i < 4 * TILE_W * NSH / 4; i += NTHR) {
            int row = i / (TILE_W * NSH / 4);            // 0..3
            int rem = i - row * (TILE_W * NSH / 4);
            float4* dst = (float4*)(out +
                ((size_t)(b * HH + h0 + 4 * g + row) * WW + w0) * NSH);
            dst[rem] = src[i];
        }
    }
}

extern "C" void kernel_launch(void* const* d_in, const int* in_sizes, int n_in,
                              void* d_out, int out_size)
{
    const float* FM0 = (const float*)d_in[0];
    const float* FM1 = (const float*)d_in[1];
    float* out = (float*)d_out;

    // Host-side, idempotent, capture-safe (proven in round 10).
    cudaFuncSetAttribute(corr_kernel,
                         cudaFuncAttributeMaxDynamicSharedMemorySize, SMEM_BYTES);

    dim3 grid(WW / TILE_W, HH / TILE_H, BATCH);  // (3,12,8) = 288 blocks, 2 CTAs/SM, one wave
    dim3 block(8, TILE_H, 3);                     // 192 threads
    corr_kernel<<<grid, block, SMEM_BYTES>>>(FM0, FM1, out);
}

// round 13
// speedup vs baseline: 1.0243x; 1.0243x over previous
#include <cuda_runtime.h>
#include <cstdint>

#define BATCH 8
#define CH    256
#define HH    96
#define WW    96
#define HW    (HH*WW)
#define DMAX  4
#define DD    9
#define NSH   81
#define TILE_W 32
#define TILE_H 8
#define NTHR  192                       // (8,8,3)
#define CC    2
#define NCHUNK (CH/CC)                  // 128
#define HALO_H 16
#define HALO_W 40                       // pure LDS.128 phases are contiguous 128B rows
#define F1_WORDS (CC*HALO_H*HALO_W)     // 1280
#define F0_WORDS (CC*TILE_H*TILE_W)     // 512
#define BUF_WORDS (F1_WORDS+F0_WORDS)   // 1792
#define SMEM_WORDS 10368                // max(3*BUF_WORDS, 4*TILE_W*NSH epilogue staging)
#define NF16_F1 (F1_WORDS/4)            // 320 16B copies -> 1 + 1 predicated per thread
#define NF16_F0 (F0_WORDS/4)            // 128 16B copies -> threads 0..127 do one

typedef unsigned long long u64;

__device__ __forceinline__ void cp16z(uint32_t dst, const void* src, int sz) {
    asm volatile("cp.async.cg.shared.global [%0], [%1], 16, %2;\n"
                 :: "r"(dst), "l"(src), "r"(sz));
}
__device__ __forceinline__ void cp16(uint32_t dst, const void* src) {
    asm volatile("cp.async.cg.shared.global [%0], [%1], 16;\n"
                 :: "r"(dst), "l"(src));
}
__device__ __forceinline__ void lds128(u64& a, u64& b, uint32_t addr) {
    asm volatile("ld.shared.v2.b64 {%0, %1}, [%2];"
                 : "=l"(a), "=l"(b) : "r"(addr));
}
__device__ __forceinline__ void ffma2(u64& acc, u64 a, u64 b) {
    asm("fma.rn.f32x2 %0, %1, %2, %3;" : "=l"(acc) : "l"(a), "l"(b), "l"(acc));
}
__device__ __forceinline__ u64 pack2(float x, float y) {
    u64 d; asm("mov.b64 %0, {%1, %2};" : "=l"(d) : "f"(x), "f"(y)); return d;
}
__device__ __forceinline__ void unpack2(u64 d, float& x, float& y) {
    asm("mov.b64 {%0, %1}, %2;" : "=f"(x), "=f"(y) : "l"(d));
}
__device__ __forceinline__ float lo32(u64 d) { float x,y; unpack2(d,x,y); return x; }
__device__ __forceinline__ float hi32(u64 d) { float x,y; unpack2(d,x,y); return y; }

__global__ __launch_bounds__(NTHR, 2)
void corr_kernel(const float* __restrict__ FM0,
                 const float* __restrict__ FM1,
                 float* __restrict__ out)
{
    __shared__ alignas(16) float smem[SMEM_WORDS];   // 41472 B

    const int tx  = threadIdx.x;          // 0..7  : 4 pixels each
    const int ty  = threadIdx.y;          // 0..7  : pixel row
    const int tz  = threadIdx.z;          // 0..2  : shift-row group (di = 3tz..3tz+2)
    const int tid = (tz * TILE_H + ty) * 8 + tx;
    const int w0  = blockIdx.x * TILE_W;
    const int h0  = blockIdx.y * TILE_H;
    const int b   = blockIdx.z;

    // ---- FM1 halo gather table: 1 + 1 predicated 16B cp.async per thread ----
    int dstw[2], srcw[2];
#pragma unroll
    for (int j = 0; j < 2; j++) {
        int idx = tid + NTHR * j;             // valid iff < 320
        int cc  = idx / (HALO_H * (HALO_W/4));
        int rem = idx - cc * (HALO_H * (HALO_W/4));
        int r   = rem / (HALO_W/4);
        int c4  = rem - r * (HALO_W/4);
        dstw[j] = (cc * HALO_H + r) * HALO_W + 4 * c4;
        int gh = h0 - DMAX + r;
        int gw = w0 - DMAX + 4 * c4;          // 4-aligned: fully in or out of [0,96)
        srcw[j] = ((unsigned)gh < HH && (unsigned)gw < WW)
                    ? cc * HW + gh * WW + gw : -1;
    }
    const bool f1v1 = (tid < NF16_F1 - NTHR); // tid < 128

    // ---- FM0 stage mapping: 16B copies (128 total; threads 0..127 do one) ----
    const float* f0base = FM0 + (size_t)b * CH * HW;
    int f0dst; size_t f0off;
    {
        int idx = tid;                        // valid iff < 128
        int cc  = idx >> 6;
        int rem = idx & 63;
        int row = rem >> 3;
        int c4  = rem & 7;
        f0dst = F1_WORDS + (cc * TILE_H + row) * TILE_W + 4 * c4;
        f0off = (size_t)cc * HW + (size_t)(h0 + row) * WW + w0 + 4 * c4;
    }
    const bool f0v = (tid < NF16_F0);         // tid < 128

    const float* f1b = FM1 + (size_t)b * CH * HW;
    const uint32_t sbase = (uint32_t)__cvta_generic_to_shared(smem);

    auto issue = [&](int c0, int buf) {
        uint32_t base = sbase + (uint32_t)(buf * BUF_WORDS) * 4u;
        {
            int sw = srcw[0];
            const float* s = f1b + (size_t)c0 * HW + (sw < 0 ? 0 : sw);
            cp16z(base + (uint32_t)dstw[0] * 4u, s, sw < 0 ? 0 : 16);
        }
        if (f1v1) {
            int sw = srcw[1];
            const float* s = f1b + (size_t)c0 * HW + (sw < 0 ? 0 : sw);
            cp16z(base + (uint32_t)dstw[1] * 4u, s, sw < 0 ? 0 : 16);
        }
        if (f0v)
            cp16(base + (uint32_t)f0dst * 4u, f0base + f0off + (size_t)c0 * HW);
        asm volatile("cp.async.commit_group;\n" ::: "memory");
    };

    // Accumulators: P[r][px][pair], S[r][px]  (3 rows x 4 px x (4 f32x2 + 1 scalar))
    u64   P[3][4][4];
    float S[3][4];
#pragma unroll
    for (int r = 0; r < 3; r++) {
#pragma unroll
        for (int i = 0; i < 4; i++) {
            S[r][i] = 0.f;
#pragma unroll
            for (int p = 0; p < 4; p++) P[r][i][p] = 0ull;
        }
    }

    // byte offset of this thread's row base within a buffer
    const uint32_t rowbyte0 = (uint32_t)(((ty + 3 * tz) * HALO_W + 4 * tx) * 4);

    issue(0, 0);
    issue(CC, 1);

    int cur = 0;                              // buffer holding chunk ci
#pragma unroll 1
    for (int ci = 0; ci < NCHUNK; ci++) {
        if (ci < NCHUNK - 1)
            asm volatile("cp.async.wait_group 1;\n" ::: "memory");
        else
            asm volatile("cp.async.wait_group 0;\n" ::: "memory");
        __syncthreads();      // chunk ci fully staged; all threads done computing ci-1

        // issue ci+2 into the buffer chunk ci-1 used (safe after the barrier)
        if (ci + 2 < NCHUNK) {
            int nb = cur + 2; if (nb >= 3) nb -= 3;
            issue((ci + 2) * CC, nb);
        }

        const float* sb = &smem[cur * BUF_WORDS];
        const uint32_t sboff = sbase + (uint32_t)(cur * BUF_WORDS) * 4u + rowbyte0;
#pragma unroll
        for (int cc = 0; cc < CC; cc++) {
            float4 f0 = *(const float4*)(sb + F1_WORDS +
                                         (cc * TILE_H + ty) * TILE_W + 4 * tx);
            const u64 fa0 = pack2(f0.x, f0.x);
            const u64 fa1 = pack2(f0.y, f0.y);
            const u64 fa2 = pack2(f0.z, f0.z);
            const u64 fa3 = pack2(f0.w, f0.w);
            const uint32_t rowa = sboff + (uint32_t)(cc * HALO_H * HALO_W) * 4u;
#pragma unroll
            for (int r = 0; r < 3; r++) {
                const uint32_t a = rowa + (uint32_t)(r * HALO_W) * 4u;
                u64 v0, v1, v2, v3, v4, v5;
                lds128(v0, v1, a);
                lds128(v2, v3, a + 16);
                lds128(v4, v5, a + 32);
                // px0 (cols 4tx+0..8): pairs v0..v3, scalar dj8 = v4.lo
                ffma2(P[r][0][0], fa0, v0); ffma2(P[r][0][1], fa0, v1);
                ffma2(P[r][0][2], fa0, v2); ffma2(P[r][0][3], fa0, v3);
                S[r][0] = fmaf(f0.x, lo32(v4), S[r][0]);
                // px1 (cols 4tx+1..9): scalar dj0 = v0.hi, pairs v1..v4
                ffma2(P[r][1][0], fa1, v1); ffma2(P[r][1][1], fa1, v2);
                ffma2(P[r][1][2], fa1, v3); ffma2(P[r][1][3], fa1, v4);
                S[r][1] = fmaf(f0.y, hi32(v0), S[r][1]);
                // px2 (cols 4tx+2..10): pairs v1..v4, scalar dj8 = v5.lo
                ffma2(P[r][2][0], fa2, v1); ffma2(P[r][2][1], fa2, v2);
                ffma2(P[r][2][2], fa2, v3); ffma2(P[r][2][3], fa2, v4);
                S[r][2] = fmaf(f0.z, lo32(v5), S[r][2]);
                // px3 (cols 4tx+3..11): scalar dj0 = v1.hi, pairs v2..v5
                ffma2(P[r][3][0], fa3, v2); ffma2(P[r][3][1], fa3, v3);
                ffma2(P[r][3][2], fa3, v4); ffma2(P[r][3][3], fa3, v5);
                S[r][3] = fmaf(f0.w, hi32(v1), S[r][3]);
            }
        }

        cur = cur + 1; if (cur >= 3) cur = 0;
    }

    // ---- coalesced output: 4 tile-rows per staging pass (2 passes) ----
#pragma unroll 1
    for (int g = 0; g < 2; g++) {
        __syncthreads();   // pass 0: all compute reads done; pass 1: all copies done
        if ((ty >> 2) == g) {
            float* st = &smem[(size_t)((ty & 3) * TILE_W + 4 * tx) * NSH];
#pragma unroll
            for (int r = 0; r < 3; r++) {
                const int base = (3 * tz + r) * DD;
                float x, y;
#pragma unroll
                for (int p = 0; p < 4; p++) {
                    unpack2(P[r][0][p], x, y);
                    st[0 * NSH + base + 2 * p]     = x;
                    st[0 * NSH + base + 2 * p + 1] = y;
                    unpack2(P[r][1][p], x, y);
                    st[1 * NSH + base + 2 * p + 1] = x;
                    st[1 * NSH + base + 2 * p + 2] = y;
                    unpack2(P[r][2][p], x, y);
                    st[2 * NSH + base + 2 * p]     = x;
                    st[2 * NSH + base + 2 * p + 1] = y;
                    unpack2(P[r][3][p], x, y);
                    st[3 * NSH + base + 2 * p + 1] = x;
                    st[3 * NSH + base + 2 * p + 2] = y;
                }
                st[0 * NSH + base + 8] = S[r][0];
                st[1 * NSH + base + 0] = S[r][1];
                st[2 * NSH + base + 8] = S[r][2];
                st[3 * NSH + base + 0] = S[r][3];
            }
        }
        __syncthreads();
        // copy 4 rows (10368 words) to gmem; out rows stride WW*NSH
        const float4* src = (const float4*)smem;
        for (int i = tid; i < 4 * TILE_W * NSH / 4; i += NTHR) {
            int row = i / (TILE_W * NSH / 4);            // 0..3
            int rem = i - row * (TILE_W * NSH / 4);
            float4* dst = (float4*)(out +
                ((size_t)(b * HH + h0 + 4 * g + row) * WW + w0) * NSH);
            dst[rem] = src[i];
        }
    }
}

extern "C" void kernel_launch(void* const* d_in, const int* in_sizes, int n_in,
                              void* d_out, int out_size)
{
    const float* FM0 = (const float*)d_in[0];
    const float* FM1 = (const float*)d_in[1];
    float* out = (float*)d_out;

    dim3 grid(WW / TILE_W, HH / TILE_H, BATCH);  // (3,12,8) = 288 blocks, 2 CTAs/SM, one wave
    dim3 block(8, TILE_H, 3);                     // 192 threads
    corr_kernel<<<grid, block>>>(FM0, FM1, out);
}

// round 14
// speedup vs baseline: 1.0470x; 1.0221x over previous
#include <cuda_runtime.h>
#include <cstdint>

#define BATCH 8
#define CH    256
#define HH    96
#define WW    96
#define HW    (HH*WW)
#define DMAX  4
#define DD    9
#define NSH   81
#define TILE_W 32
#define TILE_H 8
#define NTHR  192                       // (8,8,3)
#define CC    4
#define NCHUNK (CH/CC)                  // 64
#define HALO_H 16
#define HALO_W 40                       // pure LDS.128 phases are contiguous 128B rows
#define F1_WORDS (CC*HALO_H*HALO_W)     // 2560
#define F0_WORDS (CC*TILE_H*TILE_W)     // 1024
#define BUF_WORDS (F1_WORDS+F0_WORDS)   // 3584
#define NBUF 4
#define SMEM_BYTES (NBUF*BUF_WORDS*4)   // 57344 B per CTA (dynamic); 2 CTAs/SM fits
#define NF16_F1 (F1_WORDS/4)            // 640 16B copies -> 3 + 1 predicated per thread
#define NF16_F0 (F0_WORDS/4)            // 256 16B copies

typedef unsigned long long u64;

__device__ __forceinline__ void cp16z(uint32_t dst, const void* src, int sz) {
    asm volatile("cp.async.cg.shared.global [%0], [%1], 16, %2;\n"
                 :: "r"(dst), "l"(src), "r"(sz));
}
__device__ __forceinline__ void cp16(uint32_t dst, const void* src) {
    asm volatile("cp.async.cg.shared.global [%0], [%1], 16;\n"
                 :: "r"(dst), "l"(src));
}
__device__ __forceinline__ void lds128(u64& a, u64& b, uint32_t addr) {
    asm volatile("ld.shared.v2.b64 {%0, %1}, [%2];"
                 : "=l"(a), "=l"(b) : "r"(addr));
}
__device__ __forceinline__ void ffma2(u64& acc, u64 a, u64 b) {
    asm("fma.rn.f32x2 %0, %1, %2, %3;" : "=l"(acc) : "l"(a), "l"(b), "l"(acc));
}
__device__ __forceinline__ u64 pack2(float x, float y) {
    u64 d; asm("mov.b64 %0, {%1, %2};" : "=l"(d) : "f"(x), "f"(y)); return d;
}
__device__ __forceinline__ void unpack2(u64 d, float& x, float& y) {
    asm("mov.b64 {%0, %1}, %2;" : "=f"(x), "=f"(y) : "l"(d));
}
__device__ __forceinline__ float lo32(u64 d) { float x,y; unpack2(d,x,y); return x; }
__device__ __forceinline__ float hi32(u64 d) { float x,y; unpack2(d,x,y); return y; }

__global__ __launch_bounds__(NTHR, 2)
void corr_kernel(const float* __restrict__ FM0,
                 const float* __restrict__ FM1,
                 float* __restrict__ out)
{
    extern __shared__ float smem[];     // NBUF * BUF_WORDS words

    const int tx  = threadIdx.x;          // 0..7  : 4 pixels each
    const int ty  = threadIdx.y;          // 0..7  : pixel row
    const int tz  = threadIdx.z;          // 0..2  : shift-row group (di = 3tz..3tz+2)
    const int tid = (tz * TILE_H + ty) * 8 + tx;
    const int w0  = blockIdx.x * TILE_W;
    const int h0  = blockIdx.y * TILE_H;
    const int b   = blockIdx.z;

    // ---- FM1 halo gather table: 3 + 1 predicated 16B cp.async per thread ----
    int dstw[4], srcw[4];
#pragma unroll
    for (int j = 0; j < 4; j++) {
        int idx = tid + NTHR * j;             // valid iff < 640
        int cc  = idx / (HALO_H * (HALO_W/4));
        int rem = idx - cc * (HALO_H * (HALO_W/4));
        int r   = rem / (HALO_W/4);
        int c4  = rem - r * (HALO_W/4);
        dstw[j] = (cc * HALO_H + r) * HALO_W + 4 * c4;
        int gh = h0 - DMAX + r;
        int gw = w0 - DMAX + 4 * c4;          // 4-aligned: fully in or out of [0,96)
        srcw[j] = ((unsigned)gh < HH && (unsigned)gw < WW)
                    ? cc * HW + gh * WW + gw : -1;
    }
    const bool f1v3 = (tid < NF16_F1 - 3 * NTHR); // tid < 64

    // ---- FM0 stage mapping: 16B copies (256 total; threads 0..63 do two) ----
    const float* f0base = FM0 + (size_t)b * CH * HW;
    int f0dst[2]; size_t f0off[2];
#pragma unroll
    for (int j = 0; j < 2; j++) {
        int idx = tid + NTHR * j;             // valid iff < 256
        int cc  = idx >> 6;
        int rem = idx & 63;
        int row = rem >> 3;
        int c4  = rem & 7;
        f0dst[j] = F1_WORDS + (cc * TILE_H + row) * TILE_W + 4 * c4;
        f0off[j] = (size_t)cc * HW + (size_t)(h0 + row) * WW + w0 + 4 * c4;
    }
    const bool f0v1 = (tid < NF16_F0 - NTHR); // tid < 64

    const float* f1b = FM1 + (size_t)b * CH * HW;
    const uint32_t sbase = (uint32_t)__cvta_generic_to_shared(smem);

    auto issue = [&](int c0, int buf) {
        uint32_t base = sbase + (uint32_t)(buf * BUF_WORDS) * 4u;
#pragma unroll
        for (int j = 0; j < 4; j++) {
            if (j < 3 || f1v3) {
                int sw = srcw[j];
                const float* s = f1b + (size_t)c0 * HW + (sw < 0 ? 0 : sw);
                cp16z(base + (uint32_t)dstw[j] * 4u, s, sw < 0 ? 0 : 16);
            }
        }
        cp16(base + (uint32_t)f0dst[0] * 4u, f0base + f0off[0] + (size_t)c0 * HW);
        if (f0v1)
            cp16(base + (uint32_t)f0dst[1] * 4u, f0base + f0off[1] + (size_t)c0 * HW);
        asm volatile("cp.async.commit_group;\n" ::: "memory");
    };

    // Accumulators: P[r][px][pair], S[r][px]  (3 rows x 4 px x (4 f32x2 + 1 scalar))
    u64   P[3][4][4];
    float S[3][4];
#pragma unroll
    for (int r = 0; r < 3; r++) {
#pragma unroll
        for (int i = 0; i < 4; i++) {
            S[r][i] = 0.f;
#pragma unroll
            for (int p = 0; p < 4; p++) P[r][i][p] = 0ull;
        }
    }

    // byte offset of this thread's row base within a buffer
    const uint32_t rowbyte0 = (uint32_t)(((ty + 3 * tz) * HALO_W + 4 * tx) * 4);

    // ---- prologue: stage chunks 0..2 into bufs 0..2 (3 deep) ----
    issue(0 * CC, 0);
    issue(1 * CC, 1);
    issue(2 * CC, 2);

#pragma unroll 1
    for (int ci = 0; ci < NCHUNK; ci++) {
        // Wait until chunk ci's fill is complete. Outstanding beyond ci is
        // min(2, NCHUNK-1-ci) groups; with <=N-pending semantics the tail
        // must tighten N or the last fills would not be awaited.
        if (ci < NCHUNK - 2)
            asm volatile("cp.async.wait_group 2;\n" ::: "memory");
        else if (ci == NCHUNK - 2)
            asm volatile("cp.async.wait_group 1;\n" ::: "memory");
        else
            asm volatile("cp.async.wait_group 0;\n" ::: "memory");
        __syncthreads();      // chunk ci staged; all threads done reading ci-1

        // issue ci+3 into the buffer chunk ci-1 used (freed by the barrier)
        if (ci + 3 < NCHUNK)
            issue((ci + 3) * CC, (ci + 3) & 3);

        const int buf = ci & 3;
        const float* sb = &smem[buf * BUF_WORDS];
        const uint32_t sboff = sbase + (uint32_t)(buf * BUF_WORDS) * 4u + rowbyte0;
#pragma unroll
        for (int cc = 0; cc < CC; cc++) {
            float4 f0 = *(const float4*)(sb + F1_WORDS +
                                         (cc * TILE_H + ty) * TILE_W + 4 * tx);
            const u64 fa0 = pack2(f0.x, f0.x);
            const u64 fa1 = pack2(f0.y, f0.y);
            const u64 fa2 = pack2(f0.z, f0.z);
            const u64 fa3 = pack2(f0.w, f0.w);
            const uint32_t rowa = sboff + (uint32_t)(cc * HALO_H * HALO_W) * 4u;
#pragma unroll
            for (int r = 0; r < 3; r++) {
                const uint32_t a = rowa + (uint32_t)(r * HALO_W) * 4u;
                u64 v0, v1, v2, v3, v4, v5;
                lds128(v0, v1, a);
                lds128(v2, v3, a + 16);
                lds128(v4, v5, a + 32);
                // px0 (cols 4tx+0..8): pairs v0..v3, scalar dj8 = v4.lo
                ffma2(P[r][0][0], fa0, v0); ffma2(P[r][0][1], fa0, v1);
                ffma2(P[r][0][2], fa0, v2); ffma2(P[r][0][3], fa0, v3);
                S[r][0] = fmaf(f0.x, lo32(v4), S[r][0]);
                // px1 (cols 4tx+1..9): scalar dj0 = v0.hi, pairs v1..v4
                ffma2(P[r][1][0], fa1, v1); ffma2(P[r][1][1], fa1, v2);
                ffma2(P[r][1][2], fa1, v3); ffma2(P[r][1][3], fa1, v4);
                S[r][1] = fmaf(f0.y, hi32(v0), S[r][1]);
                // px2 (cols 4tx+2..10): pairs v1..v4, scalar dj8 = v5.lo
                ffma2(P[r][2][0], fa2, v1); ffma2(P[r][2][1], fa2, v2);
                ffma2(P[r][2][2], fa2, v3); ffma2(P[r][2][3], fa2, v4);
                S[r][2] = fmaf(f0.z, lo32(v5), S[r][2]);
                // px3 (cols 4tx+3..11): scalar dj0 = v1.hi, pairs v2..v5
                ffma2(P[r][3][0], fa3, v2); ffma2(P[r][3][1], fa3, v3);
                ffma2(P[r][3][2], fa3, v4); ffma2(P[r][3][3], fa3, v5);
                S[r][3] = fmaf(f0.w, hi32(v1), S[r][3]);
            }
        }
    }

    // ---- coalesced output: 4 tile-rows per staging pass (2 passes) ----
#pragma unroll 1
    for (int g = 0; g < 2; g++) {
        __syncthreads();   // pass 0: all compute reads done; pass 1: all copies done
        if ((ty >> 2) == g) {
            float* st = &smem[(size_t)((ty & 3) * TILE_W + 4 * tx) * NSH];
#pragma unroll
            for (int r = 0; r < 3; r++) {
                const int base = (3 * tz + r) * DD;
                float x, y;
#pragma unroll
                for (int p = 0; p < 4; p++) {
                    unpack2(P[r][0][p], x, y);
                    st[0 * NSH + base + 2 * p]     = x;
                    st[0 * NSH + base + 2 * p + 1] = y;
                    unpack2(P[r][1][p], x, y);
                    st[1 * NSH + base + 2 * p + 1] = x;
                    st[1 * NSH + base + 2 * p + 2] = y;
                    unpack2(P[r][2][p], x, y);
                    st[2 * NSH + base + 2 * p]     = x;
                    st[2 * NSH + base + 2 * p + 1] = y;
                    unpack2(P[r][3][p], x, y);
                    st[3 * NSH + base + 2 * p + 1] = x;
                    st[3 * NSH + base + 2 * p + 2] = y;
                }
                st[0 * NSH + base + 8] = S[r][0];
                st[1 * NSH + base + 0] = S[r][1];
                st[2 * NSH + base + 8] = S[r][2];
                st[3 * NSH + base + 0] = S[r][3];
            }
        }
        __syncthreads();
        // copy 4 rows (10368 words) to gmem; out rows stride WW*NSH
        const float4* src = (const float4*)smem;
        for (int i = tid; i < 4 * TILE_W * NSH / 4; i += NTHR) {
            int row = i / (TILE_W * NSH / 4);            // 0..3
            int rem = i - row * (TILE_W * NSH / 4);
            float4* dst = (float4*)(out +
                ((size_t)(b * HH + h0 + 4 * g + row) * WW + w0) * NSH);
            dst[rem] = src[i];
        }
    }
}

extern "C" void kernel_launch(void* const* d_in, const int* in_sizes, int n_in,
                              void* d_out, int out_size)
{
    const float* FM0 = (const float*)d_in[0];
    const float* FM1 = (const float*)d_in[1];
    float* out = (float*)d_out;

    // Host-side, idempotent, capture-safe (proven in rounds 10/12).
    cudaFuncSetAttribute(corr_kernel,
                         cudaFuncAttributeMaxDynamicSharedMemorySize, SMEM_BYTES);

    dim3 grid(WW / TILE_W, HH / TILE_H, BATCH);  // (3,12,8) = 288 blocks, 2 CTAs/SM, one wave
    dim3 block(8, TILE_H, 3);                     // 192 threads
    corr_kernel<<<grid, block, SMEM_BYTES>>>(FM0, FM1, out);
}